// round 2
// baseline (speedup 1.0000x reference)
#include <cuda_runtime.h>

#define B_   2
#define T_   2048
#define C_   2048
#define NH   16
#define HD   128
#define ROWS (B_ * T_)          // 4096
#define QKVN (3 * C_)           // 6144

// Scratch (device globals: allocation-free rule)
__device__ float g_qkv[(size_t)ROWS * QKVN];   // ~100.7 MB
__device__ float g_y[(size_t)ROWS * C_];       // ~33.6 MB

// ---------------------------------------------------------------------------
// GEMM + bias: C[M,N] = A[M,K] @ B[K,N] + bias[N]
// 128x128 tile, BK=16, 256 threads, 8x8 microtile. M,N,K all multiples.
// ---------------------------------------------------------------------------
__global__ __launch_bounds__(256) void gemm_bias_kernel(
    const float* __restrict__ A, const float* __restrict__ Bm,
    const float* __restrict__ bias, float* __restrict__ Cm,
    int M, int N, int K)
{
    __shared__ float As[16][132];   // transposed: As[k][m]
    __shared__ float Bs[16][132];   // Bs[k][n]

    const int bx = blockIdx.x, by = blockIdx.y;
    const int tid = threadIdx.x;
    const int tx = tid & 15, ty = tid >> 4;
    const int mreg = ty * 8, nreg = tx * 8;

    const int arow = tid >> 2;            // 0..63 (+64)
    const int acol = (tid & 3) * 4;       // k: 0,4,8,12
    const int brow = tid >> 5;            // 0..7 (+8)
    const int bcol = (tid & 31) * 4;      // n: 0..124

    const float* Ab = A + (size_t)(by * 128) * K;
    const float* Bb = Bm + bx * 128;

    float acc[8][8];
#pragma unroll
    for (int i = 0; i < 8; i++)
#pragma unroll
        for (int j = 0; j < 8; j++) acc[i][j] = 0.0f;

    for (int kb = 0; kb < K; kb += 16) {
#pragma unroll
        for (int r = 0; r < 2; r++) {
            int m = arow + r * 64;
            float4 av = *(const float4*)(Ab + (size_t)m * K + kb + acol);
            As[acol + 0][m] = av.x;
            As[acol + 1][m] = av.y;
            As[acol + 2][m] = av.z;
            As[acol + 3][m] = av.w;
        }
#pragma unroll
        for (int r = 0; r < 2; r++) {
            int kr = brow + r * 8;
            *(float4*)(&Bs[kr][bcol]) =
                *(const float4*)(Bb + (size_t)(kb + kr) * N + bcol);
        }
        __syncthreads();

#pragma unroll
        for (int k = 0; k < 16; k++) {
            float4 a0 = *(const float4*)(&As[k][mreg]);
            float4 a1 = *(const float4*)(&As[k][mreg + 4]);
            float4 b0 = *(const float4*)(&Bs[k][nreg]);
            float4 b1 = *(const float4*)(&Bs[k][nreg + 4]);
            float av[8] = {a0.x, a0.y, a0.z, a0.w, a1.x, a1.y, a1.z, a1.w};
            float bv[8] = {b0.x, b0.y, b0.z, b0.w, b1.x, b1.y, b1.z, b1.w};
#pragma unroll
            for (int i = 0; i < 8; i++)
#pragma unroll
                for (int j = 0; j < 8; j++)
                    acc[i][j] = fmaf(av[i], bv[j], acc[i][j]);
        }
        __syncthreads();
    }

    // Epilogue: bias hoisted (loaded once per thread)
    float4 bv0 = *(const float4*)(bias + bx * 128 + nreg);
    float4 bv1 = *(const float4*)(bias + bx * 128 + nreg + 4);
#pragma unroll
    for (int i = 0; i < 8; i++) {
        size_t row = (size_t)(by * 128 + mreg + i);
        float4 c0, c1;
        c0.x = acc[i][0] + bv0.x; c0.y = acc[i][1] + bv0.y;
        c0.z = acc[i][2] + bv0.z; c0.w = acc[i][3] + bv0.w;
        c1.x = acc[i][4] + bv1.x; c1.y = acc[i][5] + bv1.y;
        c1.z = acc[i][6] + bv1.z; c1.w = acc[i][7] + bv1.w;
        *(float4*)(Cm + row * N + bx * 128 + nreg)     = c0;
        *(float4*)(Cm + row * N + bx * 128 + nreg + 4) = c1;
    }
}

// ---------------------------------------------------------------------------
// Flash attention (fp32, causal). BQ=64, BK=64, HD=128, 128 threads.
// smem: sQt[128][68] | sKt[128][68] (aliased by Pst[64][68]) | sV[64][132]
// ---------------------------------------------------------------------------
#define FLASH_SMEM 103424
#define QP 68
#define VP 132

__global__ __launch_bounds__(128) void flash_kernel(
    const float* __restrict__ qkv, float* __restrict__ y)
{
    extern __shared__ float sm[];
    float* sQt = sm;              // 128*68 = 8704 floats
    float* sKt = sm + 8704;       // 128*68 (Pst aliases first 64*68)
    float* sV  = sm + 17408;      // 64*132 = 8448 floats
    float* Pst = sKt;

    const int qt = blockIdx.x, h = blockIdx.y, b = blockIdx.z;
    const int tid = threadIdx.x;
    const int tx = tid & 7, ty = tid >> 3;    // tx 0..7, ty 0..15
    const int q0 = ty * 4;                    // 4 query rows / thread
    const int k8 = tx * 8;                    // 8 keys / thread (S phase)
    const int d16 = tx * 16;                  // 16 dims / thread (O phase)

    const int rs = QKVN;
    const float scale = 0.08838834764831845f; // 1/sqrt(128)

    const int lq = tid >> 1;                  // 0..63 row loaded
    const int ldb = (tid & 1) * 64;           // dim half

    // Load Q tile transposed
    {
        const float* qp = qkv + ((size_t)(b * T_ + qt * 64 + lq)) * rs + h * HD + ldb;
#pragma unroll
        for (int it = 0; it < 16; it++) {
            float4 v = *(const float4*)(qp + it * 4);
            int d = ldb + it * 4;
            sQt[(d + 0) * QP + lq] = v.x;
            sQt[(d + 1) * QP + lq] = v.y;
            sQt[(d + 2) * QP + lq] = v.z;
            sQt[(d + 3) * QP + lq] = v.w;
        }
    }

    float m[4], l[4], o[4][16];
#pragma unroll
    for (int i = 0; i < 4; i++) {
        m[i] = -1e30f; l[i] = 0.0f;
#pragma unroll
        for (int t = 0; t < 16; t++) o[i][t] = 0.0f;
    }

    for (int kt = 0; kt <= qt; kt++) {
        __syncthreads();  // previous tile's PV reads done before overwrite

        // Load K (transposed) and V tiles
        {
            const float* kp = qkv + ((size_t)(b * T_ + kt * 64 + lq)) * rs
                              + C_ + h * HD + ldb;
            const float* vp = kp + C_;
#pragma unroll
            for (int it = 0; it < 16; it++) {
                int d = ldb + it * 4;
                float4 kv = *(const float4*)(kp + it * 4);
                sKt[(d + 0) * QP + lq] = kv.x;
                sKt[(d + 1) * QP + lq] = kv.y;
                sKt[(d + 2) * QP + lq] = kv.z;
                sKt[(d + 3) * QP + lq] = kv.w;
                float4 vv = *(const float4*)(vp + it * 4);
                *(float4*)(sV + lq * VP + d) = vv;
            }
        }
        __syncthreads();

        // S = Q K^T  (4x8 per thread)
        float s[4][8];
#pragma unroll
        for (int i = 0; i < 4; i++)
#pragma unroll
            for (int j = 0; j < 8; j++) s[i][j] = 0.0f;

#pragma unroll 8
        for (int d = 0; d < 128; d++) {
            float4 aq = *(const float4*)(sQt + d * QP + q0);
            float4 b0 = *(const float4*)(sKt + d * QP + k8);
            float4 b1 = *(const float4*)(sKt + d * QP + k8 + 4);
            float av[4] = {aq.x, aq.y, aq.z, aq.w};
            float bv[8] = {b0.x, b0.y, b0.z, b0.w, b1.x, b1.y, b1.z, b1.w};
#pragma unroll
            for (int i = 0; i < 4; i++)
#pragma unroll
                for (int j = 0; j < 8; j++)
                    s[i][j] = fmaf(av[i], bv[j], s[i][j]);
        }

        const bool diag = (kt == qt);

        // Online softmax (row spread across 8 lanes: shuffle-reduce)
#pragma unroll
        for (int i = 0; i < 4; i++) {
            float rm = -1e30f;
#pragma unroll
            for (int j = 0; j < 8; j++) {
                float v = s[i][j] * scale;
                if (diag && (k8 + j) > (q0 + i)) v = -1e30f;
                s[i][j] = v;
                rm = fmaxf(rm, v);
            }
            rm = fmaxf(rm, __shfl_xor_sync(0xffffffffu, rm, 1));
            rm = fmaxf(rm, __shfl_xor_sync(0xffffffffu, rm, 2));
            rm = fmaxf(rm, __shfl_xor_sync(0xffffffffu, rm, 4));
            float mnew = fmaxf(m[i], rm);
            float corr = __expf(m[i] - mnew);
            float rsum = 0.0f;
#pragma unroll
            for (int j = 0; j < 8; j++) {
                float p = __expf(s[i][j] - mnew);
                s[i][j] = p;
                rsum += p;
            }
            rsum += __shfl_xor_sync(0xffffffffu, rsum, 1);
            rsum += __shfl_xor_sync(0xffffffffu, rsum, 2);
            rsum += __shfl_xor_sync(0xffffffffu, rsum, 4);
            l[i] = l[i] * corr + rsum;
            m[i] = mnew;
#pragma unroll
            for (int t = 0; t < 16; t++) o[i][t] *= corr;
        }

        __syncthreads();  // all S reads of sKt done before Pst overwrite

        // Stage P transposed: Pst[key][q]
#pragma unroll
        for (int j = 0; j < 8; j++)
#pragma unroll
            for (int i = 0; i < 4; i++)
                Pst[(k8 + j) * QP + q0 + i] = s[i][j];
        __syncthreads();

        // O += P @ V  (4x16 per thread)
#pragma unroll 4
        for (int j = 0; j < 64; j++) {
            float4 a = *(const float4*)(Pst + j * QP + q0);
            const float* vr = sV + j * VP + d16;
            float4 v0 = *(const float4*)(vr);
            float4 v1 = *(const float4*)(vr + 4);
            float4 v2 = *(const float4*)(vr + 8);
            float4 v3 = *(const float4*)(vr + 12);
            float av[4] = {a.x, a.y, a.z, a.w};
            float bv[16] = {v0.x, v0.y, v0.z, v0.w, v1.x, v1.y, v1.z, v1.w,
                            v2.x, v2.y, v2.z, v2.w, v3.x, v3.y, v3.z, v3.w};
#pragma unroll
            for (int i = 0; i < 4; i++)
#pragma unroll
                for (int t = 0; t < 16; t++)
                    o[i][t] = fmaf(av[i], bv[t], o[i][t]);
        }
    }

    // Normalize + write y (B,T,C layout)
#pragma unroll
    for (int i = 0; i < 4; i++) {
        float inv = 1.0f / l[i];
        float* yr = y + ((size_t)(b * T_ + qt * 64 + q0 + i)) * C_ + h * HD + d16;
#pragma unroll
        for (int t4 = 0; t4 < 16; t4 += 4) {
            float4 w;
            w.x = o[i][t4 + 0] * inv;
            w.y = o[i][t4 + 1] * inv;
            w.z = o[i][t4 + 2] * inv;
            w.w = o[i][t4 + 3] * inv;
            *(float4*)(yr + t4) = w;
        }
    }
}

// ---------------------------------------------------------------------------
extern "C" void kernel_launch(void* const* d_in, const int* in_sizes, int n_in,
                              void* d_out, int out_size)
{
    const float* x      = (const float*)d_in[0];
    const float* W_attn = (const float*)d_in[1];
    const float* b_attn = (const float*)d_in[2];
    const float* W_proj = (const float*)d_in[3];
    const float* b_proj = (const float*)d_in[4];
    float* out = (float*)d_out;

    float *qkv, *y;
    cudaGetSymbolAddress((void**)&qkv, g_qkv);
    cudaGetSymbolAddress((void**)&y, g_y);

    cudaFuncSetAttribute(flash_kernel,
                         cudaFuncAttributeMaxDynamicSharedMemorySize, FLASH_SMEM);

    // 1) QKV projection
    gemm_bias_kernel<<<dim3(QKVN / 128, ROWS / 128), 256>>>(
        x, W_attn, b_attn, qkv, ROWS, QKVN, C_);
    // 2) Causal flash attention
    flash_kernel<<<dim3(T_ / 64, NH, B_), 128, FLASH_SMEM>>>(qkv, y);
    // 3) Output projection
    gemm_bias_kernel<<<dim3(C_ / 128, ROWS / 128), 256>>>(
        y, W_proj, b_proj, out, ROWS, C_, C_);
}

// round 3
// speedup vs baseline: 1.4818x; 1.4818x over previous
#include <cuda_runtime.h>
#include <cstdint>

#define B_   2
#define T_   2048
#define C_   2048
#define NH   16
#define HD   128
#define ROWS (B_ * T_)          // 4096
#define QKVN (3 * C_)           // 6144

// Scratch (device globals: allocation-free rule)
__device__ float g_qkv[(size_t)ROWS * QKVN];   // ~100.7 MB
__device__ float g_y[(size_t)ROWS * C_];       // ~33.6 MB

// ---------------------------------------------------------------------------
// tf32 tensor-core GEMM + bias: C[M,N] = A[M,K] @ B[K,N] + bias[N]
// 128x128x32 tile, 256 threads (8 warps, 4x2 of 32x64), cp.async 2-stage.
// Fragments converted fp32->tf32 with cvt.rna at load time (unbiased).
// ---------------------------------------------------------------------------
#define AS_STRIDE 36            // words; %32==4 -> conflict-free A frags
#define BS_STRIDE 136           // words; %32==8 -> conflict-free B frags
#define STAGE_WORDS (128 * AS_STRIDE + 32 * BS_STRIDE)   // 4608+4352=8960
#define GEMM_SMEM (2 * STAGE_WORDS * 4)                  // 71680 B

__device__ __forceinline__ uint32_t f2tf32(float f) {
    uint32_t r;
    asm("cvt.rna.tf32.f32 %0, %1;" : "=r"(r) : "f"(f));
    return r;
}

__device__ __forceinline__ void mma_tf32(float* d, const uint32_t* a,
                                         const uint32_t* b) {
    asm volatile(
        "mma.sync.aligned.m16n8k8.row.col.f32.tf32.tf32.f32 "
        "{%0,%1,%2,%3},{%4,%5,%6,%7},{%8,%9},{%0,%1,%2,%3};\n"
        : "+f"(d[0]), "+f"(d[1]), "+f"(d[2]), "+f"(d[3])
        : "r"(a[0]), "r"(a[1]), "r"(a[2]), "r"(a[3]), "r"(b[0]), "r"(b[1]));
}

#define CP_ASYNC16(dst, src) \
    asm volatile("cp.async.cg.shared.global [%0], [%1], 16;\n" :: "r"(dst), "l"(src))
#define CP_COMMIT() asm volatile("cp.async.commit_group;\n")
#define CP_WAIT1()  asm volatile("cp.async.wait_group 1;\n")

__global__ __launch_bounds__(256, 2) void gemm_tf32_kernel(
    const float* __restrict__ A, const float* __restrict__ Bm,
    const float* __restrict__ bias, float* __restrict__ Cm,
    int M, int N, int K)
{
    extern __shared__ float sh[];

    const int tid = threadIdx.x;
    const int lane = tid & 31, warp = tid >> 5;
    const int gr = lane >> 2, gc = lane & 3;       // fragment group coords
    const int wm = (warp >> 1) * 32, wn = (warp & 1) * 64;
    const int bx = blockIdx.x, by = blockIdx.y;

    // Load mappings (per-thread 4x 16B cp.async for A and B)
    const int ar = tid >> 1, ac = (tid & 1) * 16;      // A: row 0..127, col 0/16
    const int br = tid >> 3, bc = (tid & 7) * 16;      // B: row 0..31, col 0..112

    const float* Ag = A + (size_t)(by * 128 + ar) * K + ac;
    const float* Bg = Bm + (size_t)br * N + bx * 128 + bc;

    const uint32_t sb = (uint32_t)__cvta_generic_to_shared(sh);
    const int NK = K / 32;

    float acc[2][8][4];
#pragma unroll
    for (int t = 0; t < 2; t++)
#pragma unroll
        for (int j = 0; j < 8; j++)
#pragma unroll
            for (int q = 0; q < 4; q++) acc[t][j][q] = 0.0f;

    // --- preload stages 0 and 1 ---
#pragma unroll
    for (int p = 0; p < 2; p++) {
        uint32_t adst = sb + (p * STAGE_WORDS + ar * AS_STRIDE + ac) * 4;
        uint32_t bdst = sb + (p * STAGE_WORDS + 128 * AS_STRIDE + br * BS_STRIDE + bc) * 4;
        const float* asrc = Ag + p * 32;
        const float* bsrc = Bg + (size_t)p * 32 * N;
#pragma unroll
        for (int v = 0; v < 4; v++) {
            CP_ASYNC16(adst + v * 16, asrc + v * 4);
            CP_ASYNC16(bdst + v * 16, bsrc + v * 4);
        }
        CP_COMMIT();
    }

    int stage = 0;
    for (int kb = 0; kb < NK; kb++) {
        CP_WAIT1();
        __syncthreads();

        const float* Asb = sh + stage * STAGE_WORDS;
        const float* Bsb = Asb + 128 * AS_STRIDE;

#pragma unroll
        for (int ks = 0; ks < 4; ks++) {
            const int k0 = ks * 8;
            uint32_t af[2][4], bf[8][2];
#pragma unroll
            for (int t = 0; t < 2; t++) {
                const float* ap = Asb + (wm + t * 16 + gr) * AS_STRIDE + k0 + gc;
                af[t][0] = f2tf32(ap[0]);
                af[t][1] = f2tf32(ap[8 * AS_STRIDE]);
                af[t][2] = f2tf32(ap[4]);
                af[t][3] = f2tf32(ap[8 * AS_STRIDE + 4]);
            }
#pragma unroll
            for (int j = 0; j < 8; j++) {
                const float* bp = Bsb + (k0 + gc) * BS_STRIDE + wn + j * 8 + gr;
                bf[j][0] = f2tf32(bp[0]);
                bf[j][1] = f2tf32(bp[4 * BS_STRIDE]);
            }
#pragma unroll
            for (int t = 0; t < 2; t++)
#pragma unroll
                for (int j = 0; j < 8; j++)
                    mma_tf32(acc[t][j], af[t], bf[j]);
        }

        __syncthreads();

        // refill the just-consumed stage with tile kb+2
        const int kn = kb + 2;
        if (kn < NK) {
            uint32_t adst = sb + (stage * STAGE_WORDS + ar * AS_STRIDE + ac) * 4;
            uint32_t bdst = sb + (stage * STAGE_WORDS + 128 * AS_STRIDE + br * BS_STRIDE + bc) * 4;
            const float* asrc = Ag + kn * 32;
            const float* bsrc = Bg + (size_t)kn * 32 * N;
#pragma unroll
            for (int v = 0; v < 4; v++) {
                CP_ASYNC16(adst + v * 16, asrc + v * 4);
                CP_ASYNC16(bdst + v * 16, bsrc + v * 4);
            }
        }
        CP_COMMIT();
        stage ^= 1;
    }

    // --- epilogue: bias + store (float2 per fragment row-pair) ---
    const int col0 = bx * 128 + wn + 2 * gc;
    const int row0 = by * 128 + wm + gr;
    float2 bv[8];
#pragma unroll
    for (int j = 0; j < 8; j++)
        bv[j] = *(const float2*)(bias + col0 + j * 8);

#pragma unroll
    for (int t = 0; t < 2; t++) {
        const int r = row0 + t * 16;
#pragma unroll
        for (int j = 0; j < 8; j++) {
            float2 v0, v1;
            v0.x = acc[t][j][0] + bv[j].x;
            v0.y = acc[t][j][1] + bv[j].y;
            v1.x = acc[t][j][2] + bv[j].x;
            v1.y = acc[t][j][3] + bv[j].y;
            *(float2*)(Cm + (size_t)r * N + col0 + j * 8) = v0;
            *(float2*)(Cm + (size_t)(r + 8) * N + col0 + j * 8) = v1;
        }
    }
}

// ---------------------------------------------------------------------------
// Flash attention (fp32, causal). BQ=64, BK=64, HD=128, 128 threads.
// smem: sQt[128][68] | sKt[128][68] (aliased by Pst[64][68]) | sV[64][132]
// ---------------------------------------------------------------------------
#define FLASH_SMEM 103424
#define QP 68
#define VP 132

__global__ __launch_bounds__(128) void flash_kernel(
    const float* __restrict__ qkv, float* __restrict__ y)
{
    extern __shared__ float sm[];
    float* sQt = sm;              // 128*68 = 8704 floats
    float* sKt = sm + 8704;       // 128*68 (Pst aliases first 64*68)
    float* sV  = sm + 17408;      // 64*132 = 8448 floats
    float* Pst = sKt;

    const int qt = blockIdx.x, h = blockIdx.y, b = blockIdx.z;
    const int tid = threadIdx.x;
    const int tx = tid & 7, ty = tid >> 3;    // tx 0..7, ty 0..15
    const int q0 = ty * 4;                    // 4 query rows / thread
    const int k8 = tx * 8;                    // 8 keys / thread (S phase)
    const int d16 = tx * 16;                  // 16 dims / thread (O phase)

    const int rs = QKVN;
    const float scale = 0.08838834764831845f; // 1/sqrt(128)

    const int lq = tid >> 1;                  // 0..63 row loaded
    const int ldb = (tid & 1) * 64;           // dim half

    // Load Q tile transposed
    {
        const float* qp = qkv + ((size_t)(b * T_ + qt * 64 + lq)) * rs + h * HD + ldb;
#pragma unroll
        for (int it = 0; it < 16; it++) {
            float4 v = *(const float4*)(qp + it * 4);
            int d = ldb + it * 4;
            sQt[(d + 0) * QP + lq] = v.x;
            sQt[(d + 1) * QP + lq] = v.y;
            sQt[(d + 2) * QP + lq] = v.z;
            sQt[(d + 3) * QP + lq] = v.w;
        }
    }

    float m[4], l[4], o[4][16];
#pragma unroll
    for (int i = 0; i < 4; i++) {
        m[i] = -1e30f; l[i] = 0.0f;
#pragma unroll
        for (int t = 0; t < 16; t++) o[i][t] = 0.0f;
    }

    for (int kt = 0; kt <= qt; kt++) {
        __syncthreads();  // previous tile's PV reads done before overwrite

        // Load K (transposed) and V tiles
        {
            const float* kp = qkv + ((size_t)(b * T_ + kt * 64 + lq)) * rs
                              + C_ + h * HD + ldb;
            const float* vp = kp + C_;
#pragma unroll
            for (int it = 0; it < 16; it++) {
                int d = ldb + it * 4;
                float4 kv = *(const float4*)(kp + it * 4);
                sKt[(d + 0) * QP + lq] = kv.x;
                sKt[(d + 1) * QP + lq] = kv.y;
                sKt[(d + 2) * QP + lq] = kv.z;
                sKt[(d + 3) * QP + lq] = kv.w;
                float4 vv = *(const float4*)(vp + it * 4);
                *(float4*)(sV + lq * VP + d) = vv;
            }
        }
        __syncthreads();

        // S = Q K^T  (4x8 per thread)
        float s[4][8];
#pragma unroll
        for (int i = 0; i < 4; i++)
#pragma unroll
            for (int j = 0; j < 8; j++) s[i][j] = 0.0f;

#pragma unroll 8
        for (int d = 0; d < 128; d++) {
            float4 aq = *(const float4*)(sQt + d * QP + q0);
            float4 b0 = *(const float4*)(sKt + d * QP + k8);
            float4 b1 = *(const float4*)(sKt + d * QP + k8 + 4);
            float av[4] = {aq.x, aq.y, aq.z, aq.w};
            float bv[8] = {b0.x, b0.y, b0.z, b0.w, b1.x, b1.y, b1.z, b1.w};
#pragma unroll
            for (int i = 0; i < 4; i++)
#pragma unroll
                for (int j = 0; j < 8; j++)
                    s[i][j] = fmaf(av[i], bv[j], s[i][j]);
        }

        const bool diag = (kt == qt);

        // Online softmax (row spread across 8 lanes: shuffle-reduce)
#pragma unroll
        for (int i = 0; i < 4; i++) {
            float rm = -1e30f;
#pragma unroll
            for (int j = 0; j < 8; j++) {
                float v = s[i][j] * scale;
                if (diag && (k8 + j) > (q0 + i)) v = -1e30f;
                s[i][j] = v;
                rm = fmaxf(rm, v);
            }
            rm = fmaxf(rm, __shfl_xor_sync(0xffffffffu, rm, 1));
            rm = fmaxf(rm, __shfl_xor_sync(0xffffffffu, rm, 2));
            rm = fmaxf(rm, __shfl_xor_sync(0xffffffffu, rm, 4));
            float mnew = fmaxf(m[i], rm);
            float corr = __expf(m[i] - mnew);
            float rsum = 0.0f;
#pragma unroll
            for (int j = 0; j < 8; j++) {
                float p = __expf(s[i][j] - mnew);
                s[i][j] = p;
                rsum += p;
            }
            rsum += __shfl_xor_sync(0xffffffffu, rsum, 1);
            rsum += __shfl_xor_sync(0xffffffffu, rsum, 2);
            rsum += __shfl_xor_sync(0xffffffffu, rsum, 4);
            l[i] = l[i] * corr + rsum;
            m[i] = mnew;
#pragma unroll
            for (int t = 0; t < 16; t++) o[i][t] *= corr;
        }

        __syncthreads();  // all S reads of sKt done before Pst overwrite

        // Stage P transposed: Pst[key][q]
#pragma unroll
        for (int j = 0; j < 8; j++)
#pragma unroll
            for (int i = 0; i < 4; i++)
                Pst[(k8 + j) * QP + q0 + i] = s[i][j];
        __syncthreads();

        // O += P @ V  (4x16 per thread)
#pragma unroll 4
        for (int j = 0; j < 64; j++) {
            float4 a = *(const float4*)(Pst + j * QP + q0);
            const float* vr = sV + j * VP + d16;
            float4 v0 = *(const float4*)(vr);
            float4 v1 = *(const float4*)(vr + 4);
            float4 v2 = *(const float4*)(vr + 8);
            float4 v3 = *(const float4*)(vr + 12);
            float av[4] = {a.x, a.y, a.z, a.w};
            float bv[16] = {v0.x, v0.y, v0.z, v0.w, v1.x, v1.y, v1.z, v1.w,
                            v2.x, v2.y, v2.z, v2.w, v3.x, v3.y, v3.z, v3.w};
#pragma unroll
            for (int i = 0; i < 4; i++)
#pragma unroll
                for (int t = 0; t < 16; t++)
                    o[i][t] = fmaf(av[i], bv[t], o[i][t]);
        }
    }

    // Normalize + write y (B,T,C layout)
#pragma unroll
    for (int i = 0; i < 4; i++) {
        float inv = 1.0f / l[i];
        float* yr = y + ((size_t)(b * T_ + qt * 64 + q0 + i)) * C_ + h * HD + d16;
#pragma unroll
        for (int t4 = 0; t4 < 16; t4 += 4) {
            float4 w;
            w.x = o[i][t4 + 0] * inv;
            w.y = o[i][t4 + 1] * inv;
            w.z = o[i][t4 + 2] * inv;
            w.w = o[i][t4 + 3] * inv;
            *(float4*)(yr + t4) = w;
        }
    }
}

// ---------------------------------------------------------------------------
extern "C" void kernel_launch(void* const* d_in, const int* in_sizes, int n_in,
                              void* d_out, int out_size)
{
    const float* x      = (const float*)d_in[0];
    const float* W_attn = (const float*)d_in[1];
    const float* b_attn = (const float*)d_in[2];
    const float* W_proj = (const float*)d_in[3];
    const float* b_proj = (const float*)d_in[4];
    float* out = (float*)d_out;

    float *qkv, *y;
    cudaGetSymbolAddress((void**)&qkv, g_qkv);
    cudaGetSymbolAddress((void**)&y, g_y);

    cudaFuncSetAttribute(gemm_tf32_kernel,
                         cudaFuncAttributeMaxDynamicSharedMemorySize, GEMM_SMEM);
    cudaFuncSetAttribute(flash_kernel,
                         cudaFuncAttributeMaxDynamicSharedMemorySize, FLASH_SMEM);

    // 1) QKV projection (tf32 tensor cores)
    gemm_tf32_kernel<<<dim3(QKVN / 128, ROWS / 128), 256, GEMM_SMEM>>>(
        x, W_attn, b_attn, qkv, ROWS, QKVN, C_);
    // 2) Causal flash attention
    flash_kernel<<<dim3(T_ / 64, NH, B_), 128, FLASH_SMEM>>>(qkv, y);
    // 3) Output projection (tf32 tensor cores)
    gemm_tf32_kernel<<<dim3(C_ / 128, ROWS / 128), 256, GEMM_SMEM>>>(
        y, W_proj, b_proj, out, ROWS, C_, C_);
}

// round 6
// speedup vs baseline: 2.9956x; 2.0216x over previous
#include <cuda_runtime.h>
#include <cstdint>

#define B_   2
#define T_   2048
#define C_   2048
#define NH   16
#define HD   128
#define ROWS (B_ * T_)          // 4096
#define QKVN (3 * C_)           // 6144

// Scratch (device globals: allocation-free rule)
__device__ float g_qkv[(size_t)ROWS * QKVN];   // ~100.7 MB
__device__ float g_y[(size_t)ROWS * C_];       // ~33.6 MB

// ---------------------------------------------------------------------------
// Common PTX helpers
// ---------------------------------------------------------------------------
__device__ __forceinline__ uint32_t f2tf32(float f) {
    uint32_t r;
    asm("cvt.rna.tf32.f32 %0, %1;" : "=r"(r) : "f"(f));
    return r;
}

__device__ __forceinline__ void mma_tf32(float* d, const uint32_t* a,
                                         const uint32_t* b) {
    asm volatile(
        "mma.sync.aligned.m16n8k8.row.col.f32.tf32.tf32.f32 "
        "{%0,%1,%2,%3},{%4,%5,%6,%7},{%8,%9},{%0,%1,%2,%3};\n"
        : "+f"(d[0]), "+f"(d[1]), "+f"(d[2]), "+f"(d[3])
        : "r"(a[0]), "r"(a[1]), "r"(a[2]), "r"(a[3]), "r"(b[0]), "r"(b[1]));
}

#define CP_ASYNC16(dst, src) \
    asm volatile("cp.async.cg.shared.global [%0], [%1], 16;\n" :: "r"(dst), "l"(src))
#define CP_COMMIT() asm volatile("cp.async.commit_group;\n")
#define CP_WAIT1()  asm volatile("cp.async.wait_group 1;\n")

// ---------------------------------------------------------------------------
// tf32 tensor-core GEMM + bias: C[M,N] = A[M,K] @ B[K,N] + bias[N]
// 128x128x32 tile, 256 threads (8 warps, 4x2 of 32x64), cp.async 2-stage.
// ---------------------------------------------------------------------------
#define AS_STRIDE 36
#define BS_STRIDE 136
#define STAGE_WORDS (128 * AS_STRIDE + 32 * BS_STRIDE)   // 8960
#define GEMM_SMEM (2 * STAGE_WORDS * 4)                  // 71680 B

__global__ __launch_bounds__(256, 2) void gemm_tf32_kernel(
    const float* __restrict__ A, const float* __restrict__ Bm,
    const float* __restrict__ bias, float* __restrict__ Cm,
    int M, int N, int K)
{
    extern __shared__ float sh[];

    const int tid = threadIdx.x;
    const int lane = tid & 31, warp = tid >> 5;
    const int gr = lane >> 2, gc = lane & 3;
    const int wm = (warp >> 1) * 32, wn = (warp & 1) * 64;
    const int bx = blockIdx.x, by = blockIdx.y;

    const int ar = tid >> 1, ac = (tid & 1) * 16;
    const int br = tid >> 3, bc = (tid & 7) * 16;

    const float* Ag = A + (size_t)(by * 128 + ar) * K + ac;
    const float* Bg = Bm + (size_t)br * N + bx * 128 + bc;

    const uint32_t sb = (uint32_t)__cvta_generic_to_shared(sh);
    const int NK = K / 32;

    float acc[2][8][4];
#pragma unroll
    for (int t = 0; t < 2; t++)
#pragma unroll
        for (int j = 0; j < 8; j++)
#pragma unroll
            for (int q = 0; q < 4; q++) acc[t][j][q] = 0.0f;

#pragma unroll
    for (int p = 0; p < 2; p++) {
        uint32_t adst = sb + (p * STAGE_WORDS + ar * AS_STRIDE + ac) * 4;
        uint32_t bdst = sb + (p * STAGE_WORDS + 128 * AS_STRIDE + br * BS_STRIDE + bc) * 4;
        const float* asrc = Ag + p * 32;
        const float* bsrc = Bg + (size_t)p * 32 * N;
#pragma unroll
        for (int v = 0; v < 4; v++) {
            CP_ASYNC16(adst + v * 16, asrc + v * 4);
            CP_ASYNC16(bdst + v * 16, bsrc + v * 4);
        }
        CP_COMMIT();
    }

    int stage = 0;
    for (int kb = 0; kb < NK; kb++) {
        CP_WAIT1();
        __syncthreads();

        const float* Asb = sh + stage * STAGE_WORDS;
        const float* Bsb = Asb + 128 * AS_STRIDE;

#pragma unroll
        for (int ks = 0; ks < 4; ks++) {
            const int k0 = ks * 8;
            uint32_t af[2][4], bf[8][2];
#pragma unroll
            for (int t = 0; t < 2; t++) {
                const float* ap = Asb + (wm + t * 16 + gr) * AS_STRIDE + k0 + gc;
                af[t][0] = f2tf32(ap[0]);
                af[t][1] = f2tf32(ap[8 * AS_STRIDE]);
                af[t][2] = f2tf32(ap[4]);
                af[t][3] = f2tf32(ap[8 * AS_STRIDE + 4]);
            }
#pragma unroll
            for (int j = 0; j < 8; j++) {
                const float* bp = Bsb + (k0 + gc) * BS_STRIDE + wn + j * 8 + gr;
                bf[j][0] = f2tf32(bp[0]);
                bf[j][1] = f2tf32(bp[4 * BS_STRIDE]);
            }
#pragma unroll
            for (int t = 0; t < 2; t++)
#pragma unroll
                for (int j = 0; j < 8; j++)
                    mma_tf32(acc[t][j], af[t], bf[j]);
        }

        __syncthreads();

        const int kn = kb + 2;
        if (kn < NK) {
            uint32_t adst = sb + (stage * STAGE_WORDS + ar * AS_STRIDE + ac) * 4;
            uint32_t bdst = sb + (stage * STAGE_WORDS + 128 * AS_STRIDE + br * BS_STRIDE + bc) * 4;
            const float* asrc = Ag + kn * 32;
            const float* bsrc = Bg + (size_t)kn * 32 * N;
#pragma unroll
            for (int v = 0; v < 4; v++) {
                CP_ASYNC16(adst + v * 16, asrc + v * 4);
                CP_ASYNC16(bdst + v * 16, bsrc + v * 4);
            }
        }
        CP_COMMIT();
        stage ^= 1;
    }

    const int col0 = bx * 128 + wn + 2 * gc;
    const int row0 = by * 128 + wm + gr;
    float2 bv[8];
#pragma unroll
    for (int j = 0; j < 8; j++)
        bv[j] = *(const float2*)(bias + col0 + j * 8);

#pragma unroll
    for (int t = 0; t < 2; t++) {
        const int r = row0 + t * 16;
#pragma unroll
        for (int j = 0; j < 8; j++) {
            float2 v0, v1;
            v0.x = acc[t][j][0] + bv[j].x;
            v0.y = acc[t][j][1] + bv[j].y;
            v1.x = acc[t][j][2] + bv[j].x;
            v1.y = acc[t][j][3] + bv[j].y;
            *(float2*)(Cm + (size_t)r * N + col0 + j * 8) = v0;
            *(float2*)(Cm + (size_t)(r + 8) * N + col0 + j * 8) = v1;
        }
    }
}

// ---------------------------------------------------------------------------
// Tensor-core flash attention (tf32 mma, causal).
// BQ=128, BK=64, HD=128, 256 threads (8 warps x 16 query rows).
// smem (tf32 words): sQ[128][132] | sK[64][132] | sVt[128][68] | sP[128][68]
// ---------------------------------------------------------------------------
#define QS 132
#define KS 132
#define VTS 68
#define PS 68
#define SQ_OFF  0
#define SK_OFF  (128 * QS)                 // 16896
#define SVT_OFF (SK_OFF + 64 * KS)         // 25344
#define SP_OFF  (SVT_OFF + 128 * VTS)      // 34048
#define FLASH_WORDS (SP_OFF + 128 * PS)    // 42752
#define FLASH_SMEM (FLASH_WORDS * 4)       // 171008 B

__global__ __launch_bounds__(256, 1) void flash_tc_kernel(
    const float* __restrict__ qkv, float* __restrict__ y)
{
    extern __shared__ uint32_t su[];
    uint32_t* sQ  = su + SQ_OFF;
    uint32_t* sK  = su + SK_OFF;
    uint32_t* sVt = su + SVT_OFF;
    uint32_t* sP  = su + SP_OFF;

    const int qt = blockIdx.x, h = blockIdx.y, b = blockIdx.z;
    const int tid = threadIdx.x;
    const int lane = tid & 31, warp = tid >> 5;
    const int gr = lane >> 2, gc = lane & 3;
    const int m0 = warp * 16;
    const float scale = 0.08838834764831845f; // 1/sqrt(128)

    // ---- load Q tile (cvt to tf32, STS.128) ----
    {
        const int row = tid & 127;
        const int d0 = (tid >> 7) * 64;
        const float* qp = qkv + ((size_t)(b * T_ + qt * 128 + row)) * QKVN
                          + h * HD + d0;
        uint32_t* dst = sQ + row * QS + d0;
#pragma unroll
        for (int it = 0; it < 16; it++) {
            float4 v = *(const float4*)(qp + it * 4);
            uint4 w;
            w.x = f2tf32(v.x); w.y = f2tf32(v.y);
            w.z = f2tf32(v.z); w.w = f2tf32(v.w);
            *(uint4*)(dst + it * 4) = w;
        }
    }

    float o[16][4];
#pragma unroll
    for (int j = 0; j < 16; j++)
#pragma unroll
        for (int c = 0; c < 4; c++) o[j][c] = 0.0f;
    float mrow[2] = {-1e30f, -1e30f};
    float lrow[2] = {0.0f, 0.0f};

    const int ktmax = 2 * qt + 1;
    for (int kt = 0; kt <= ktmax; kt++) {
        __syncthreads();   // prev iter's sK/sVt reads complete

        // ---- load K (row-major) and V (transposed) tiles ----
        {
            const int row = tid & 63;
            const int d0 = (tid >> 6) * 32;
            const float* kp = qkv + ((size_t)(b * T_ + kt * 64 + row)) * QKVN
                              + C_ + h * HD + d0;
            const float* vp = kp + C_;
            uint32_t* kdst = sK + row * KS + d0;
#pragma unroll
            for (int it = 0; it < 8; it++) {
                float4 v = *(const float4*)(kp + it * 4);
                uint4 w;
                w.x = f2tf32(v.x); w.y = f2tf32(v.y);
                w.z = f2tf32(v.z); w.w = f2tf32(v.w);
                *(uint4*)(kdst + it * 4) = w;
            }
#pragma unroll
            for (int it = 0; it < 8; it++) {
                float4 v = *(const float4*)(vp + it * 4);
                const int d = d0 + it * 4;
                sVt[(d + 0) * VTS + row] = f2tf32(v.x);
                sVt[(d + 1) * VTS + row] = f2tf32(v.y);
                sVt[(d + 2) * VTS + row] = f2tf32(v.z);
                sVt[(d + 3) * VTS + row] = f2tf32(v.w);
            }
        }
        __syncthreads();

        // warps entirely left of this key block: all-masked, skip compute
        if (qt * 128 + m0 + 15 < kt * 64) continue;

        // ---- S = Q @ K^T  (m16 x n64) ----
        float s[8][4];
#pragma unroll
        for (int j = 0; j < 8; j++)
#pragma unroll
            for (int c = 0; c < 4; c++) s[j][c] = 0.0f;

#pragma unroll
        for (int ks = 0; ks < 16; ks++) {
            const int k0 = ks * 8;
            uint32_t a[4];
            const uint32_t* ap = sQ + (m0 + gr) * QS + k0 + gc;
            a[0] = ap[0];
            a[1] = ap[8 * QS];
            a[2] = ap[4];
            a[3] = ap[8 * QS + 4];
#pragma unroll
            for (int j = 0; j < 8; j++) {
                uint32_t bfr[2];
                const uint32_t* bp = sK + (j * 8 + gr) * KS + k0 + gc;
                bfr[0] = bp[0];
                bfr[1] = bp[4];
                mma_tf32(s[j], a, bfr);
            }
        }

        // ---- online softmax on fragments ----
#pragma unroll
        for (int r = 0; r < 2; r++) {
            const int qg = qt * 128 + m0 + gr + 8 * r;
            const bool need_mask = (kt * 64 + 63 > qg);
            float rm = -1e30f;
#pragma unroll
            for (int j = 0; j < 8; j++) {
#pragma unroll
                for (int c = 0; c < 2; c++) {
                    float v = s[j][2 * r + c] * scale;
                    if (need_mask && (kt * 64 + j * 8 + 2 * gc + c) > qg)
                        v = -1e30f;
                    s[j][2 * r + c] = v;
                    rm = fmaxf(rm, v);
                }
            }
            rm = fmaxf(rm, __shfl_xor_sync(0xffffffffu, rm, 1));
            rm = fmaxf(rm, __shfl_xor_sync(0xffffffffu, rm, 2));
            const float mnew = fmaxf(mrow[r], rm);
            const float corr = __expf(mrow[r] - mnew);
            float rsum = 0.0f;
#pragma unroll
            for (int j = 0; j < 8; j++) {
#pragma unroll
                for (int c = 0; c < 2; c++) {
                    float p = __expf(s[j][2 * r + c] - mnew);
                    s[j][2 * r + c] = p;
                    rsum += p;
                }
            }
            rsum += __shfl_xor_sync(0xffffffffu, rsum, 1);
            rsum += __shfl_xor_sync(0xffffffffu, rsum, 2);
            lrow[r] = lrow[r] * corr + rsum;
            mrow[r] = mnew;
#pragma unroll
            for (int j = 0; j < 16; j++) {
                o[j][2 * r + 0] *= corr;
                o[j][2 * r + 1] *= corr;
            }
        }

        // ---- stage P (tf32) into smem: own 16 rows only ----
#pragma unroll
        for (int j = 0; j < 8; j++) {
            uint2 p0, p1;
            p0.x = f2tf32(s[j][0]); p0.y = f2tf32(s[j][1]);
            p1.x = f2tf32(s[j][2]); p1.y = f2tf32(s[j][3]);
            *(uint2*)(sP + (m0 + gr) * PS + j * 8 + 2 * gc)     = p0;
            *(uint2*)(sP + (m0 + gr + 8) * PS + j * 8 + 2 * gc) = p1;
        }
        __syncwarp();

        // ---- O += P @ V  (m16 x n128, k=64) ----
#pragma unroll
        for (int ks = 0; ks < 8; ks++) {
            const int k0 = ks * 8;
            uint32_t a[4];
            const uint32_t* ap = sP + (m0 + gr) * PS + k0 + gc;
            a[0] = ap[0];
            a[1] = ap[8 * PS];
            a[2] = ap[4];
            a[3] = ap[8 * PS + 4];
#pragma unroll
            for (int j = 0; j < 16; j++) {
                uint32_t bfr[2];
                const uint32_t* bp = sVt + (j * 8 + gr) * VTS + k0 + gc;
                bfr[0] = bp[0];
                bfr[1] = bp[4];
                mma_tf32(o[j], a, bfr);
            }
        }
    }

    // ---- epilogue: O/l -> y ----
    const float inv0 = 1.0f / lrow[0];
    const float inv1 = 1.0f / lrow[1];
#pragma unroll
    for (int r = 0; r < 2; r++) {
        const float inv = r ? inv1 : inv0;
        float* yr = y + ((size_t)(b * T_ + qt * 128 + m0 + gr + 8 * r)) * C_
                    + h * HD + 2 * gc;
#pragma unroll
        for (int j = 0; j < 16; j++) {
            float2 w;
            w.x = o[j][2 * r + 0] * inv;
            w.y = o[j][2 * r + 1] * inv;
            *(float2*)(yr + j * 8) = w;
        }
    }
}

// ---------------------------------------------------------------------------
extern "C" void kernel_launch(void* const* d_in, const int* in_sizes, int n_in,
                              void* d_out, int out_size)
{
    const float* x      = (const float*)d_in[0];
    const float* W_attn = (const float*)d_in[1];
    const float* b_attn = (const float*)d_in[2];
    const float* W_proj = (const float*)d_in[3];
    const float* b_proj = (const float*)d_in[4];
    float* out = (float*)d_out;

    float *qkv, *y;
    cudaGetSymbolAddress((void**)&qkv, g_qkv);
    cudaGetSymbolAddress((void**)&y, g_y);

    cudaFuncSetAttribute(gemm_tf32_kernel,
                         cudaFuncAttributeMaxDynamicSharedMemorySize, GEMM_SMEM);
    cudaFuncSetAttribute(flash_tc_kernel,
                         cudaFuncAttributeMaxDynamicSharedMemorySize, FLASH_SMEM);

    // 1) QKV projection (tf32 tensor cores)
    gemm_tf32_kernel<<<dim3(QKVN / 128, ROWS / 128), 256, GEMM_SMEM>>>(
        x, W_attn, b_attn, qkv, ROWS, QKVN, C_);
    // 2) Causal flash attention (tf32 tensor cores)
    flash_tc_kernel<<<dim3(T_ / 128, NH, B_), 256, FLASH_SMEM>>>(qkv, y);
    // 3) Output projection (tf32 tensor cores)
    gemm_tf32_kernel<<<dim3(C_ / 128, ROWS / 128), 256, GEMM_SMEM>>>(
        y, W_proj, b_proj, out, ROWS, C_, C_);
}

// round 7
// speedup vs baseline: 3.0728x; 1.0258x over previous
#include <cuda_runtime.h>
#include <cstdint>

#define B_   2
#define T_   2048
#define C_   2048
#define NH   16
#define HD   128
#define ROWS (B_ * T_)          // 4096
#define QKVN (3 * C_)           // 6144

// Scratch (device globals: allocation-free rule)
__device__ float g_qkv[(size_t)ROWS * QKVN];   // ~100.7 MB
__device__ float g_y[(size_t)ROWS * C_];       // ~33.6 MB
__device__ float g_xc[(size_t)ROWS * C_];      // x rounded to tf32
__device__ float g_wac[(size_t)C_ * QKVN];     // W_attn rounded
__device__ float g_wpc[(size_t)C_ * C_];       // W_proj rounded

// ---------------------------------------------------------------------------
// Common PTX helpers
// ---------------------------------------------------------------------------
__device__ __forceinline__ uint32_t f2tf32(float f) {
    uint32_t r;
    asm("cvt.rna.tf32.f32 %0, %1;" : "=r"(r) : "f"(f));
    return r;
}

__device__ __forceinline__ void mma_tf32(float* d, const uint32_t* a,
                                         const uint32_t* b) {
    asm volatile(
        "mma.sync.aligned.m16n8k8.row.col.f32.tf32.tf32.f32 "
        "{%0,%1,%2,%3},{%4,%5,%6,%7},{%8,%9},{%0,%1,%2,%3};\n"
        : "+f"(d[0]), "+f"(d[1]), "+f"(d[2]), "+f"(d[3])
        : "r"(a[0]), "r"(a[1]), "r"(a[2]), "r"(a[3]), "r"(b[0]), "r"(b[1]));
}

#define CP_ASYNC16(dst, src) \
    asm volatile("cp.async.cg.shared.global [%0], [%1], 16;\n" :: "r"(dst), "l"(src))
#define CP_COMMIT() asm volatile("cp.async.commit_group;\n")
#define CP_WAIT1()  asm volatile("cp.async.wait_group 1;\n")

// ---------------------------------------------------------------------------
// Elementwise fp32 -> tf32-rounded (stored as fp32 with low 13 bits zero)
// ---------------------------------------------------------------------------
__global__ __launch_bounds__(256) void round_tf32_kernel(
    const float4* __restrict__ in, float4* __restrict__ out, int n4)
{
    int i = blockIdx.x * blockDim.x + threadIdx.x;
    if (i < n4) {
        float4 v = in[i];
        float4 w;
        w.x = __uint_as_float(f2tf32(v.x));
        w.y = __uint_as_float(f2tf32(v.y));
        w.z = __uint_as_float(f2tf32(v.z));
        w.w = __uint_as_float(f2tf32(v.w));
        out[i] = w;
    }
}

// ---------------------------------------------------------------------------
// tf32 tensor-core GEMM + bias: C[M,N] = A[M,K] @ B[K,N] + bias[N]
// Inputs MUST be pre-rounded to tf32. 256x128x32 block tile, 256 threads,
// 8 warps each 64x64 (4x2 m16n8k8 grid of 4x8 MMAs). 2-stage cp.async.
// ROUND: round the output to tf32 when writing (for downstream mma consumers).
// ---------------------------------------------------------------------------
#define AS_STRIDE 36
#define BS_STRIDE 136
#define STW (256 * AS_STRIDE + 32 * BS_STRIDE)   // 9216+4352 = 13568 words
#define GEMM_SMEM (2 * STW * 4)                  // 108544 B

template <bool ROUND>
__global__ __launch_bounds__(256, 1) void gemm_tf32_kernel(
    const float* __restrict__ A, const float* __restrict__ Bm,
    const float* __restrict__ bias, float* __restrict__ Cm,
    int M, int N, int K)
{
    extern __shared__ uint32_t sh[];

    const int tid = threadIdx.x;
    const int lane = tid & 31, warp = tid >> 5;
    const int gr = lane >> 2, gc = lane & 3;
    const int wm = (warp >> 1) * 64, wn = (warp & 1) * 64;
    const int bx = blockIdx.x, by = blockIdx.y;

    const int ar = tid >> 1, ac = (tid & 1) * 16;   // A rows ar, ar+128
    const int br = tid >> 3, bc = (tid & 7) * 16;   // B row 0..31

    const float* Ag = A + (size_t)(by * 256 + ar) * K + ac;
    const float* Bg = Bm + (size_t)br * N + bx * 128 + bc;

    const uint32_t sb = (uint32_t)__cvta_generic_to_shared(sh);
    const int NK = K / 32;

    float acc[4][8][4];
#pragma unroll
    for (int t = 0; t < 4; t++)
#pragma unroll
        for (int j = 0; j < 8; j++)
#pragma unroll
            for (int q = 0; q < 4; q++) acc[t][j][q] = 0.0f;

    // --- preload stages 0, 1 ---
#pragma unroll
    for (int p = 0; p < 2; p++) {
        uint32_t a0 = sb + (p * STW + ar * AS_STRIDE + ac) * 4;
        uint32_t a1 = sb + (p * STW + (ar + 128) * AS_STRIDE + ac) * 4;
        uint32_t bd = sb + (p * STW + 256 * AS_STRIDE + br * BS_STRIDE + bc) * 4;
        const float* as0 = Ag + p * 32;
        const float* as1 = Ag + (size_t)128 * K + p * 32;
        const float* bs  = Bg + (size_t)p * 32 * N;
#pragma unroll
        for (int v = 0; v < 4; v++) {
            CP_ASYNC16(a0 + v * 16, as0 + v * 4);
            CP_ASYNC16(a1 + v * 16, as1 + v * 4);
            CP_ASYNC16(bd + v * 16, bs + v * 4);
        }
        CP_COMMIT();
    }

    int stage = 0;
    for (int kb = 0; kb < NK; kb++) {
        CP_WAIT1();
        __syncthreads();

        const uint32_t* Asb = sh + stage * STW;
        const uint32_t* Bsb = Asb + 256 * AS_STRIDE;

#pragma unroll
        for (int ks = 0; ks < 4; ks++) {
            const int k0 = ks * 8;
            uint32_t af[4][4], bf[8][2];
#pragma unroll
            for (int t = 0; t < 4; t++) {
                const uint32_t* ap = Asb + (wm + t * 16 + gr) * AS_STRIDE + k0 + gc;
                af[t][0] = ap[0];
                af[t][1] = ap[8 * AS_STRIDE];
                af[t][2] = ap[4];
                af[t][3] = ap[8 * AS_STRIDE + 4];
            }
#pragma unroll
            for (int j = 0; j < 8; j++) {
                const uint32_t* bp = Bsb + (k0 + gc) * BS_STRIDE + wn + j * 8 + gr;
                bf[j][0] = bp[0];
                bf[j][1] = bp[4 * BS_STRIDE];
            }
#pragma unroll
            for (int t = 0; t < 4; t++)
#pragma unroll
                for (int j = 0; j < 8; j++)
                    mma_tf32(acc[t][j], af[t], bf[j]);
        }

        __syncthreads();

        const int kn = kb + 2;
        if (kn < NK) {
            uint32_t a0 = sb + (stage * STW + ar * AS_STRIDE + ac) * 4;
            uint32_t a1 = sb + (stage * STW + (ar + 128) * AS_STRIDE + ac) * 4;
            uint32_t bd = sb + (stage * STW + 256 * AS_STRIDE + br * BS_STRIDE + bc) * 4;
            const float* as0 = Ag + kn * 32;
            const float* as1 = Ag + (size_t)128 * K + kn * 32;
            const float* bs  = Bg + (size_t)kn * 32 * N;
#pragma unroll
            for (int v = 0; v < 4; v++) {
                CP_ASYNC16(a0 + v * 16, as0 + v * 4);
                CP_ASYNC16(a1 + v * 16, as1 + v * 4);
                CP_ASYNC16(bd + v * 16, bs + v * 4);
            }
        }
        CP_COMMIT();
        stage ^= 1;
    }

    // --- epilogue ---
    const int col0 = bx * 128 + wn + 2 * gc;
    const int row0 = by * 256 + wm + gr;
    float2 bv[8];
#pragma unroll
    for (int j = 0; j < 8; j++)
        bv[j] = *(const float2*)(bias + col0 + j * 8);

#pragma unroll
    for (int t = 0; t < 4; t++) {
        const int r = row0 + t * 16;
#pragma unroll
        for (int j = 0; j < 8; j++) {
            float2 v0, v1;
            v0.x = acc[t][j][0] + bv[j].x;
            v0.y = acc[t][j][1] + bv[j].y;
            v1.x = acc[t][j][2] + bv[j].x;
            v1.y = acc[t][j][3] + bv[j].y;
            if (ROUND) {
                v0.x = __uint_as_float(f2tf32(v0.x));
                v0.y = __uint_as_float(f2tf32(v0.y));
                v1.x = __uint_as_float(f2tf32(v1.x));
                v1.y = __uint_as_float(f2tf32(v1.y));
            }
            *(float2*)(Cm + (size_t)r * N + col0 + j * 8) = v0;
            *(float2*)(Cm + (size_t)(r + 8) * N + col0 + j * 8) = v1;
        }
    }
}

// ---------------------------------------------------------------------------
// Tensor-core flash attention (tf32 mma, causal). qkv is PRE-ROUNDED tf32.
// BQ=128, BK=64, HD=128, 256 threads (8 warps x 16 query rows).
// smem (words): sQ[128][132] | sK[64][132] | sVt[128][68] | sP[128][68]
// ---------------------------------------------------------------------------
#define QS 132
#define KS 132
#define VTS 68
#define PS 68
#define SQ_OFF  0
#define SK_OFF  (128 * QS)
#define SVT_OFF (SK_OFF + 64 * KS)
#define SP_OFF  (SVT_OFF + 128 * VTS)
#define FLASH_WORDS (SP_OFF + 128 * PS)
#define FLASH_SMEM (FLASH_WORDS * 4)       // 171008 B

__global__ __launch_bounds__(256, 1) void flash_tc_kernel(
    const float* __restrict__ qkv, float* __restrict__ y)
{
    extern __shared__ uint32_t su[];
    uint32_t* sQ  = su + SQ_OFF;
    uint32_t* sK  = su + SK_OFF;
    uint32_t* sVt = su + SVT_OFF;
    uint32_t* sP  = su + SP_OFF;

    const int qt = blockIdx.x, h = blockIdx.y, b = blockIdx.z;
    const int tid = threadIdx.x;
    const int lane = tid & 31, warp = tid >> 5;
    const int gr = lane >> 2, gc = lane & 3;
    const int m0 = warp * 16;
    const float scale = 0.08838834764831845f; // 1/sqrt(128)

    // ---- load Q tile (raw: already tf32-rounded) ----
    {
        const int row = tid & 127;
        const int d0 = (tid >> 7) * 64;
        const uint4* qp = (const uint4*)(qkv
            + ((size_t)(b * T_ + qt * 128 + row)) * QKVN + h * HD + d0);
        uint32_t* dst = sQ + row * QS + d0;
#pragma unroll
        for (int it = 0; it < 16; it++)
            *(uint4*)(dst + it * 4) = qp[it];
    }

    float o[16][4];
#pragma unroll
    for (int j = 0; j < 16; j++)
#pragma unroll
        for (int c = 0; c < 4; c++) o[j][c] = 0.0f;
    float mrow[2] = {-1e30f, -1e30f};
    float lrow[2] = {0.0f, 0.0f};

    const int ktmax = 2 * qt + 1;
    for (int kt = 0; kt <= ktmax; kt++) {
        __syncthreads();

        // ---- load K (row-major) and V (transposed) tiles, raw ----
        {
            const int row = tid & 63;
            const int d0 = (tid >> 6) * 32;
            const float* kp = qkv + ((size_t)(b * T_ + kt * 64 + row)) * QKVN
                              + C_ + h * HD + d0;
            const uint4* kpu = (const uint4*)kp;
            const float4* vp = (const float4*)(kp + C_);
            uint32_t* kdst = sK + row * KS + d0;
#pragma unroll
            for (int it = 0; it < 8; it++)
                *(uint4*)(kdst + it * 4) = kpu[it];
#pragma unroll
            for (int it = 0; it < 8; it++) {
                float4 v = vp[it];
                const int d = d0 + it * 4;
                sVt[(d + 0) * VTS + row] = __float_as_uint(v.x);
                sVt[(d + 1) * VTS + row] = __float_as_uint(v.y);
                sVt[(d + 2) * VTS + row] = __float_as_uint(v.z);
                sVt[(d + 3) * VTS + row] = __float_as_uint(v.w);
            }
        }
        __syncthreads();

        if (qt * 128 + m0 + 15 < kt * 64) continue;

        // ---- S = Q @ K^T ----
        float s[8][4];
#pragma unroll
        for (int j = 0; j < 8; j++)
#pragma unroll
            for (int c = 0; c < 4; c++) s[j][c] = 0.0f;

#pragma unroll
        for (int ks = 0; ks < 16; ks++) {
            const int k0 = ks * 8;
            uint32_t a[4];
            const uint32_t* ap = sQ + (m0 + gr) * QS + k0 + gc;
            a[0] = ap[0];
            a[1] = ap[8 * QS];
            a[2] = ap[4];
            a[3] = ap[8 * QS + 4];
#pragma unroll
            for (int j = 0; j < 8; j++) {
                uint32_t bfr[2];
                const uint32_t* bp = sK + (j * 8 + gr) * KS + k0 + gc;
                bfr[0] = bp[0];
                bfr[1] = bp[4];
                mma_tf32(s[j], a, bfr);
            }
        }

        // ---- online softmax ----
#pragma unroll
        for (int r = 0; r < 2; r++) {
            const int qg = qt * 128 + m0 + gr + 8 * r;
            const bool need_mask = (kt * 64 + 63 > qg);
            float rm = -1e30f;
#pragma unroll
            for (int j = 0; j < 8; j++) {
#pragma unroll
                for (int c = 0; c < 2; c++) {
                    float v = s[j][2 * r + c] * scale;
                    if (need_mask && (kt * 64 + j * 8 + 2 * gc + c) > qg)
                        v = -1e30f;
                    s[j][2 * r + c] = v;
                    rm = fmaxf(rm, v);
                }
            }
            rm = fmaxf(rm, __shfl_xor_sync(0xffffffffu, rm, 1));
            rm = fmaxf(rm, __shfl_xor_sync(0xffffffffu, rm, 2));
            const float mnew = fmaxf(mrow[r], rm);
            const float corr = __expf(mrow[r] - mnew);
            float rsum = 0.0f;
#pragma unroll
            for (int j = 0; j < 8; j++) {
#pragma unroll
                for (int c = 0; c < 2; c++) {
                    float p = __expf(s[j][2 * r + c] - mnew);
                    s[j][2 * r + c] = p;
                    rsum += p;
                }
            }
            rsum += __shfl_xor_sync(0xffffffffu, rsum, 1);
            rsum += __shfl_xor_sync(0xffffffffu, rsum, 2);
            lrow[r] = lrow[r] * corr + rsum;
            mrow[r] = mnew;
#pragma unroll
            for (int j = 0; j < 16; j++) {
                o[j][2 * r + 0] *= corr;
                o[j][2 * r + 1] *= corr;
            }
        }

        // ---- stage P (tf32) ----
#pragma unroll
        for (int j = 0; j < 8; j++) {
            uint2 p0, p1;
            p0.x = f2tf32(s[j][0]); p0.y = f2tf32(s[j][1]);
            p1.x = f2tf32(s[j][2]); p1.y = f2tf32(s[j][3]);
            *(uint2*)(sP + (m0 + gr) * PS + j * 8 + 2 * gc)     = p0;
            *(uint2*)(sP + (m0 + gr + 8) * PS + j * 8 + 2 * gc) = p1;
        }
        __syncwarp();

        // ---- O += P @ V ----
#pragma unroll
        for (int ks = 0; ks < 8; ks++) {
            const int k0 = ks * 8;
            uint32_t a[4];
            const uint32_t* ap = sP + (m0 + gr) * PS + k0 + gc;
            a[0] = ap[0];
            a[1] = ap[8 * PS];
            a[2] = ap[4];
            a[3] = ap[8 * PS + 4];
#pragma unroll
            for (int j = 0; j < 16; j++) {
                uint32_t bfr[2];
                const uint32_t* bp = sVt + (j * 8 + gr) * VTS + k0 + gc;
                bfr[0] = bp[0];
                bfr[1] = bp[4];
                mma_tf32(o[j], a, bfr);
            }
        }
    }

    // ---- epilogue: O/l -> y, rounded to tf32 (proj consumes via mma) ----
    const float inv0 = 1.0f / lrow[0];
    const float inv1 = 1.0f / lrow[1];
#pragma unroll
    for (int r = 0; r < 2; r++) {
        const float inv = r ? inv1 : inv0;
        float* yr = y + ((size_t)(b * T_ + qt * 128 + m0 + gr + 8 * r)) * C_
                    + h * HD + 2 * gc;
#pragma unroll
        for (int j = 0; j < 16; j++) {
            float2 w;
            w.x = __uint_as_float(f2tf32(o[j][2 * r + 0] * inv));
            w.y = __uint_as_float(f2tf32(o[j][2 * r + 1] * inv));
            *(float2*)(yr + j * 8) = w;
        }
    }
}

// ---------------------------------------------------------------------------
extern "C" void kernel_launch(void* const* d_in, const int* in_sizes, int n_in,
                              void* d_out, int out_size)
{
    const float* x      = (const float*)d_in[0];
    const float* W_attn = (const float*)d_in[1];
    const float* b_attn = (const float*)d_in[2];
    const float* W_proj = (const float*)d_in[3];
    const float* b_proj = (const float*)d_in[4];
    float* out = (float*)d_out;

    float *qkv, *y, *xc, *wac, *wpc;
    cudaGetSymbolAddress((void**)&qkv, g_qkv);
    cudaGetSymbolAddress((void**)&y, g_y);
    cudaGetSymbolAddress((void**)&xc, g_xc);
    cudaGetSymbolAddress((void**)&wac, g_wac);
    cudaGetSymbolAddress((void**)&wpc, g_wpc);

    cudaFuncSetAttribute(gemm_tf32_kernel<true>,
                         cudaFuncAttributeMaxDynamicSharedMemorySize, GEMM_SMEM);
    cudaFuncSetAttribute(gemm_tf32_kernel<false>,
                         cudaFuncAttributeMaxDynamicSharedMemorySize, GEMM_SMEM);
    cudaFuncSetAttribute(flash_tc_kernel,
                         cudaFuncAttributeMaxDynamicSharedMemorySize, FLASH_SMEM);

    // 0) pre-round operands to tf32
    {
        int n4x = (ROWS * C_) / 4;
        int n4a = (C_ * QKVN) / 4;
        int n4p = (C_ * C_) / 4;
        round_tf32_kernel<<<(n4x + 255) / 256, 256>>>((const float4*)x, (float4*)xc, n4x);
        round_tf32_kernel<<<(n4a + 255) / 256, 256>>>((const float4*)W_attn, (float4*)wac, n4a);
        round_tf32_kernel<<<(n4p + 255) / 256, 256>>>((const float4*)W_proj, (float4*)wpc, n4p);
    }

    // 1) QKV projection (output rounded for flash)
    gemm_tf32_kernel<true><<<dim3(QKVN / 128, ROWS / 256), 256, GEMM_SMEM>>>(
        xc, wac, b_attn, qkv, ROWS, QKVN, C_);
    // 2) Causal flash attention (writes y rounded)
    flash_tc_kernel<<<dim3(T_ / 128, NH, B_), 256, FLASH_SMEM>>>(qkv, y);
    // 3) Output projection (fp32 output)
    gemm_tf32_kernel<false><<<dim3(C_ / 128, ROWS / 256), 256, GEMM_SMEM>>>(
        y, wpc, b_proj, out, ROWS, C_, C_);
}

// round 11
// speedup vs baseline: 6.2798x; 2.0436x over previous
#include <cuda_runtime.h>
#include <cuda_fp16.h>
#include <cstdint>

#define B_   2
#define T_   2048
#define C_   2048
#define NH   16
#define HD   128
#define ROWS (B_ * T_)          // 4096
#define QKVN (3 * C_)           // 6144

// Scratch (device globals: allocation-free rule)
__device__ __half g_qkv[(size_t)ROWS * QKVN];   // 50.3 MB (fp16)
__device__ __half g_y[(size_t)ROWS * C_];       // 16.8 MB
__device__ __half g_xh[(size_t)ROWS * C_];      // x as fp16
__device__ __half g_wat[(size_t)QKVN * C_];     // W_attn^T fp16 [N][K]
__device__ __half g_wpt[(size_t)C_ * C_];       // W_proj^T fp16 [N][K]

// ---------------------------------------------------------------------------
// PTX helpers
// ---------------------------------------------------------------------------
__device__ __forceinline__ void mma_f16(float* d, const uint32_t* a,
                                        const uint32_t* b) {
    asm volatile(
        "mma.sync.aligned.m16n8k16.row.col.f32.f16.f16.f32 "
        "{%0,%1,%2,%3},{%4,%5,%6,%7},{%8,%9},{%0,%1,%2,%3};\n"
        : "+f"(d[0]), "+f"(d[1]), "+f"(d[2]), "+f"(d[3])
        : "r"(a[0]), "r"(a[1]), "r"(a[2]), "r"(a[3]), "r"(b[0]), "r"(b[1]));
}

#define CP_ASYNC16(dst, src) \
    asm volatile("cp.async.cg.shared.global [%0], [%1], 16;\n" :: "r"(dst), "l"(src))
#define CP_COMMIT() asm volatile("cp.async.commit_group;\n")
#define CP_WAIT1()  asm volatile("cp.async.wait_group 1;\n")

__device__ __forceinline__ uint32_t pack_h2(float lo, float hi) {
    __half2 h = __floats2half2_rn(lo, hi);
    return *(uint32_t*)&h;
}

// ---------------------------------------------------------------------------
// fp32 -> fp16 elementwise
// ---------------------------------------------------------------------------
__global__ __launch_bounds__(256) void f2h_kernel(
    const float4* __restrict__ in, __half2* __restrict__ out, int n4)
{
    int i = blockIdx.x * blockDim.x + threadIdx.x;
    if (i < n4) {
        float4 v = in[i];
        out[2 * i + 0] = __floats2half2_rn(v.x, v.y);
        out[2 * i + 1] = __floats2half2_rn(v.z, v.w);
    }
}

// ---------------------------------------------------------------------------
// Transpose + convert: WT[n][k] = fp16(W[k][n]).  W: [K][N] fp32 row-major.
// ---------------------------------------------------------------------------
__global__ __launch_bounds__(256) void transpose_h_kernel(
    const float* __restrict__ W, __half* __restrict__ WT, int K, int N)
{
    __shared__ float t[32][33];
    const int tx = threadIdx.x, ty = threadIdx.y;
    const int n = blockIdx.x * 32 + tx;
    const int k0 = blockIdx.y * 32;
#pragma unroll
    for (int i = 0; i < 4; i++)
        t[ty + i * 8][tx] = W[(size_t)(k0 + ty + i * 8) * N + n];
    __syncthreads();
    const int k = k0 + tx;
    const int n0 = blockIdx.x * 32;
#pragma unroll
    for (int i = 0; i < 4; i++)
        WT[(size_t)(n0 + ty + i * 8) * K + k] =
            __float2half_rn(t[tx][ty + i * 8]);
}

// ---------------------------------------------------------------------------
// fp16 tensor-core GEMM + bias: C[M,N] = A[M,K] @ BT[N,K]^T + bias[N]
// A, BT fp16 K-major. Block tile 256x128, K-chunk 32, 8 warps (each 64x64),
// 2-stage cp.async. Output fp16 (OUTHALF) or fp32.
// smem rows padded to 80B (40 halves): 16B-aligned + conflict-free frags.
// ---------------------------------------------------------------------------
#define GROW 80                          // bytes per smem row (32 halves + pad)
#define STG_A (256 * GROW)               // 20480
#define STG_B (128 * GROW)               // 10240
#define STG_BYTES (STG_A + STG_B)        // 30720
#define GEMM_SMEM (2 * STG_BYTES)        // 61440

template <bool OUTHALF>
__global__ __launch_bounds__(256, 1) void gemm_f16_kernel(
    const __half* __restrict__ A, const __half* __restrict__ BT,
    const float* __restrict__ bias, void* __restrict__ Cv,
    int K, int NOUT)
{
    extern __shared__ uint8_t smb[];
    const uint32_t sb = (uint32_t)__cvta_generic_to_shared(smb);

    const int tid = threadIdx.x;
    const int lane = tid & 31, warp = tid >> 5;
    const int gr = lane >> 2, gc = lane & 3;
    const int wm = (warp >> 1) * 64, wn = (warp & 1) * 64;
    const int bx = blockIdx.x, by = blockIdx.y;
    const int NK = K / 32;

    // load mapping (halves): A rows {ar, ar+128} x 2x16B units; B row br x 2 units
    const int ar = tid >> 1, au = (tid & 1) * 2;
    const __half* Ag = A + (size_t)(by * 256 + ar) * K + au * 8;
    const __half* Bg = BT + (size_t)(bx * 128 + ar) * K + au * 8;

    float acc[4][8][4];
#pragma unroll
    for (int t = 0; t < 4; t++)
#pragma unroll
        for (int j = 0; j < 8; j++)
#pragma unroll
            for (int q = 0; q < 4; q++) acc[t][j][q] = 0.0f;

    // prologue: chunks 0,1
#pragma unroll
    for (int p = 0; p < 2; p++) {
        const uint32_t st = sb + p * STG_BYTES;
#pragma unroll
        for (int u = 0; u < 2; u++) {
            CP_ASYNC16(st + ar * GROW + (au + u) * 16,
                       Ag + (size_t)p * 32 + u * 8);
            CP_ASYNC16(st + (ar + 128) * GROW + (au + u) * 16,
                       Ag + (size_t)128 * K + p * 32 + u * 8);
            CP_ASYNC16(st + STG_A + ar * GROW + (au + u) * 16,
                       Bg + (size_t)p * 32 + u * 8);
        }
        CP_COMMIT();
    }

    int stage = 0;
    for (int c = 0; c < NK; c++) {
        CP_WAIT1();
        __syncthreads();

        const uint32_t Asb = sb + stage * STG_BYTES;
        const uint32_t Bsb = Asb + STG_A;

#pragma unroll
        for (int s = 0; s < 2; s++) {           // two k16 steps
            uint32_t af[4][4], bf[8][2];
#pragma unroll
            for (int t = 0; t < 4; t++) {
                const uint32_t ap = Asb + (wm + t * 16 + gr) * GROW + s * 32 + gc * 4;
                af[t][0] = *(const uint32_t*)(smb + (ap - sb));
                af[t][1] = *(const uint32_t*)(smb + (ap - sb) + 8 * GROW);
                af[t][2] = *(const uint32_t*)(smb + (ap - sb) + 16);
                af[t][3] = *(const uint32_t*)(smb + (ap - sb) + 8 * GROW + 16);
            }
#pragma unroll
            for (int j = 0; j < 8; j++) {
                const uint32_t bp = Bsb + (wn + j * 8 + gr) * GROW + s * 32 + gc * 4;
                bf[j][0] = *(const uint32_t*)(smb + (bp - sb));
                bf[j][1] = *(const uint32_t*)(smb + (bp - sb) + 16);
            }
#pragma unroll
            for (int t = 0; t < 4; t++)
#pragma unroll
                for (int j = 0; j < 8; j++)
                    mma_f16(acc[t][j], af[t], bf[j]);
        }

        __syncthreads();

        const int kn = c + 2;
        if (kn < NK) {
            const uint32_t st = sb + stage * STG_BYTES;
#pragma unroll
            for (int u = 0; u < 2; u++) {
                CP_ASYNC16(st + ar * GROW + (au + u) * 16,
                           Ag + (size_t)kn * 32 + u * 8);
                CP_ASYNC16(st + (ar + 128) * GROW + (au + u) * 16,
                           Ag + (size_t)128 * K + kn * 32 + u * 8);
                CP_ASYNC16(st + STG_A + ar * GROW + (au + u) * 16,
                           Bg + (size_t)kn * 32 + u * 8);
            }
        }
        CP_COMMIT();
        stage ^= 1;
    }

    // epilogue
    const int col0 = bx * 128 + wn + 2 * gc;
    const int row0 = by * 256 + wm + gr;
    float2 bv[8];
#pragma unroll
    for (int j = 0; j < 8; j++)
        bv[j] = *(const float2*)(bias + col0 + j * 8);

#pragma unroll
    for (int t = 0; t < 4; t++) {
        const int r = row0 + t * 16;
#pragma unroll
        for (int j = 0; j < 8; j++) {
            float v0x = acc[t][j][0] + bv[j].x;
            float v0y = acc[t][j][1] + bv[j].y;
            float v1x = acc[t][j][2] + bv[j].x;
            float v1y = acc[t][j][3] + bv[j].y;
            if (OUTHALF) {
                __half* Cm = (__half*)Cv;
                *(__half2*)(Cm + (size_t)r * NOUT + col0 + j * 8) =
                    __floats2half2_rn(v0x, v0y);
                *(__half2*)(Cm + (size_t)(r + 8) * NOUT + col0 + j * 8) =
                    __floats2half2_rn(v1x, v1y);
            } else {
                float* Cm = (float*)Cv;
                float2 w0 = {v0x, v0y}, w1 = {v1x, v1y};
                *(float2*)(Cm + (size_t)r * NOUT + col0 + j * 8) = w0;
                *(float2*)(Cm + (size_t)(r + 8) * NOUT + col0 + j * 8) = w1;
            }
        }
    }
}

// ---------------------------------------------------------------------------
// fp16 tensor-core flash attention (causal). qkv fp16.
// BQ=128, BK=64, HD=128, 256 threads (8 warps x 16 query rows).
// smem bytes: sQ[128][272] | sK[64][272] | sVt[128][144] | sP[128][144]
// ---------------------------------------------------------------------------
#define SQB 272                 // 128 halves + pad = 136 halves
#define SKB 272
#define SVB 144                 // 64 keys + pad = 72 halves
#define SPB 144
#define SQ_OFF  0
#define SK_OFF  (128 * SQB)                  // 34816
#define SVT_OFF (SK_OFF + 64 * SKB)          // 52224
#define SP_OFF  (SVT_OFF + 128 * SVB)        // 70656
#define FLASH_SMEM (SP_OFF + 128 * SPB)      // 89088

__global__ __launch_bounds__(256, 1) void flash_f16_kernel(
    const __half* __restrict__ qkv, __half* __restrict__ y)
{
    extern __shared__ uint8_t smb[];

    const int qt = blockIdx.x, h = blockIdx.y, b = blockIdx.z;
    const int tid = threadIdx.x;
    const int lane = tid & 31, warp = tid >> 5;
    const int gr = lane >> 2, gc = lane & 3;
    const int m0 = warp * 16;
    const float scale = 0.08838834764831845f; // 1/sqrt(128)

    // ---- load Q tile ----
    {
        const int row = tid & 127;
        const int d0 = (tid >> 7) * 64;       // halves
        const uint4* qp = (const uint4*)(qkv
            + ((size_t)(b * T_ + qt * 128 + row)) * QKVN + h * HD + d0);
        uint8_t* dst = smb + SQ_OFF + row * SQB + d0 * 2;
#pragma unroll
        for (int it = 0; it < 8; it++)
            *(uint4*)(dst + it * 16) = qp[it];
    }

    float o[16][4];
#pragma unroll
    for (int j = 0; j < 16; j++)
#pragma unroll
        for (int c = 0; c < 4; c++) o[j][c] = 0.0f;
    float mrow[2] = {-1e30f, -1e30f};
    float lrow[2] = {0.0f, 0.0f};

    const int ktmax = 2 * qt + 1;
    for (int kt = 0; kt <= ktmax; kt++) {
        __syncthreads();

        // ---- load K (row-major) + V (transposed) ----
        {
            const int row = tid & 63;
            const int d0 = (tid >> 6) * 32;   // halves
            const __half* kp = qkv + ((size_t)(b * T_ + kt * 64 + row)) * QKVN
                               + C_ + h * HD + d0;
            const uint4* kpu = (const uint4*)kp;
            const uint4* vpu = (const uint4*)(kp + 2 * C_ - C_ + C_); // v = kp + C_
            vpu = (const uint4*)(kp + C_);
            uint8_t* kdst = smb + SK_OFF + row * SKB + d0 * 2;
#pragma unroll
            for (int it = 0; it < 4; it++)
                *(uint4*)(kdst + it * 16) = kpu[it];
#pragma unroll
            for (int it = 0; it < 4; it++) {
                uint4 v = vpu[it];
                uint32_t w[4] = {v.x, v.y, v.z, v.w};
                const int dbase = d0 + it * 8;
#pragma unroll
                for (int q = 0; q < 4; q++) {
                    uint8_t* p0 = smb + SVT_OFF + (dbase + 2 * q) * SVB + row * 2;
                    uint8_t* p1 = p0 + SVB;
                    *(uint16_t*)p0 = (uint16_t)(w[q] & 0xFFFFu);
                    *(uint16_t*)p1 = (uint16_t)(w[q] >> 16);
                }
            }
        }
        __syncthreads();

        if (qt * 128 + m0 + 15 < kt * 64) continue;

        // ---- S = Q @ K^T  (8 k16 steps, n64) ----
        float s[8][4];
#pragma unroll
        for (int j = 0; j < 8; j++)
#pragma unroll
            for (int c = 0; c < 4; c++) s[j][c] = 0.0f;

#pragma unroll
        for (int ks = 0; ks < 8; ks++) {
            uint32_t a[4];
            const uint8_t* ap = smb + SQ_OFF + (m0 + gr) * SQB + ks * 32 + gc * 4;
            a[0] = *(const uint32_t*)(ap);
            a[1] = *(const uint32_t*)(ap + 8 * SQB);
            a[2] = *(const uint32_t*)(ap + 16);
            a[3] = *(const uint32_t*)(ap + 8 * SQB + 16);
#pragma unroll
            for (int j = 0; j < 8; j++) {
                uint32_t bfr[2];
                const uint8_t* bp = smb + SK_OFF + (j * 8 + gr) * SKB + ks * 32 + gc * 4;
                bfr[0] = *(const uint32_t*)(bp);
                bfr[1] = *(const uint32_t*)(bp + 16);
                mma_f16(s[j], a, bfr);
            }
        }

        // ---- online softmax ----
#pragma unroll
        for (int r = 0; r < 2; r++) {
            const int qg = qt * 128 + m0 + gr + 8 * r;
            const bool need_mask = (kt * 64 + 63 > qg);
            float rm = -1e30f;
#pragma unroll
            for (int j = 0; j < 8; j++) {
#pragma unroll
                for (int c = 0; c < 2; c++) {
                    float v = s[j][2 * r + c] * scale;
                    if (need_mask && (kt * 64 + j * 8 + 2 * gc + c) > qg)
                        v = -1e30f;
                    s[j][2 * r + c] = v;
                    rm = fmaxf(rm, v);
                }
            }
            rm = fmaxf(rm, __shfl_xor_sync(0xffffffffu, rm, 1));
            rm = fmaxf(rm, __shfl_xor_sync(0xffffffffu, rm, 2));
            const float mnew = fmaxf(mrow[r], rm);
            const float corr = __expf(mrow[r] - mnew);
            float rsum = 0.0f;
#pragma unroll
            for (int j = 0; j < 8; j++) {
#pragma unroll
                for (int c = 0; c < 2; c++) {
                    float p = __expf(s[j][2 * r + c] - mnew);
                    s[j][2 * r + c] = p;
                    rsum += p;
                }
            }
            rsum += __shfl_xor_sync(0xffffffffu, rsum, 1);
            rsum += __shfl_xor_sync(0xffffffffu, rsum, 2);
            lrow[r] = lrow[r] * corr + rsum;
            mrow[r] = mnew;
#pragma unroll
            for (int j = 0; j < 16; j++) {
                o[j][2 * r + 0] *= corr;
                o[j][2 * r + 1] *= corr;
            }
        }

        // ---- stage P (fp16) ----
#pragma unroll
        for (int j = 0; j < 8; j++) {
            uint8_t* p0 = smb + SP_OFF + (m0 + gr) * SPB + j * 16 + gc * 4;
            *(uint32_t*)p0 = pack_h2(s[j][0], s[j][1]);
            *(uint32_t*)(p0 + 8 * SPB) = pack_h2(s[j][2], s[j][3]);
        }
        __syncwarp();

        // ---- O += P @ V  (4 k16 steps, n128) ----
#pragma unroll
        for (int ks = 0; ks < 4; ks++) {
            uint32_t a[4];
            const uint8_t* ap = smb + SP_OFF + (m0 + gr) * SPB + ks * 32 + gc * 4;
            a[0] = *(const uint32_t*)(ap);
            a[1] = *(const uint32_t*)(ap + 8 * SPB);
            a[2] = *(const uint32_t*)(ap + 16);
            a[3] = *(const uint32_t*)(ap + 8 * SPB + 16);
#pragma unroll
            for (int j = 0; j < 16; j++) {
                uint32_t bfr[2];
                const uint8_t* bp = smb + SVT_OFF + (j * 8 + gr) * SVB + ks * 32 + gc * 4;
                bfr[0] = *(const uint32_t*)(bp);
                bfr[1] = *(const uint32_t*)(bp + 16);
                mma_f16(o[j], a, bfr);
            }
        }
    }

    // ---- epilogue: O/l -> y (fp16) ----
    const float inv0 = 1.0f / lrow[0];
    const float inv1 = 1.0f / lrow[1];
#pragma unroll
    for (int r = 0; r < 2; r++) {
        const float inv = r ? inv1 : inv0;
        __half* yr = y + ((size_t)(b * T_ + qt * 128 + m0 + gr + 8 * r)) * C_
                     + h * HD + 2 * gc;
#pragma unroll
        for (int j = 0; j < 16; j++)
            *(__half2*)(yr + j * 8) =
                __floats2half2_rn(o[j][2 * r + 0] * inv, o[j][2 * r + 1] * inv);
    }
}

// ---------------------------------------------------------------------------
extern "C" void kernel_launch(void* const* d_in, const int* in_sizes, int n_in,
                              void* d_out, int out_size)
{
    const float* x      = (const float*)d_in[0];
    const float* W_attn = (const float*)d_in[1];
    const float* b_attn = (const float*)d_in[2];
    const float* W_proj = (const float*)d_in[3];
    const float* b_proj = (const float*)d_in[4];
    float* out = (float*)d_out;

    __half *qkv, *y, *xh, *wat, *wpt;
    cudaGetSymbolAddress((void**)&qkv, g_qkv);
    cudaGetSymbolAddress((void**)&y, g_y);
    cudaGetSymbolAddress((void**)&xh, g_xh);
    cudaGetSymbolAddress((void**)&wat, g_wat);
    cudaGetSymbolAddress((void**)&wpt, g_wpt);

    cudaFuncSetAttribute(gemm_f16_kernel<true>,
                         cudaFuncAttributeMaxDynamicSharedMemorySize, GEMM_SMEM);
    cudaFuncSetAttribute(gemm_f16_kernel<false>,
                         cudaFuncAttributeMaxDynamicSharedMemorySize, GEMM_SMEM);
    cudaFuncSetAttribute(flash_f16_kernel,
                         cudaFuncAttributeMaxDynamicSharedMemorySize, FLASH_SMEM);

    // 0) convert operands to fp16 (x elementwise; weights transpose+convert)
    {
        int n4x = (ROWS * C_) / 4;
        f2h_kernel<<<(n4x + 255) / 256, 256>>>(
            (const float4*)x, (__half2*)xh, n4x);
        transpose_h_kernel<<<dim3(QKVN / 32, C_ / 32), dim3(32, 8)>>>(
            W_attn, wat, C_, QKVN);
        transpose_h_kernel<<<dim3(C_ / 32, C_ / 32), dim3(32, 8)>>>(
            W_proj, wpt, C_, C_);
    }

    // 1) QKV projection (fp16 mma, fp16 out)
    gemm_f16_kernel<true><<<dim3(QKVN / 128, ROWS / 256), 256, GEMM_SMEM>>>(
        xh, wat, b_attn, qkv, C_, QKVN);
    // 2) Causal flash attention (fp16 mma, fp16 y)
    flash_f16_kernel<<<dim3(T_ / 128, NH, B_), 256, FLASH_SMEM>>>(qkv, y);
    // 3) Output projection (fp16 mma, fp32 out)
    gemm_f16_kernel<false><<<dim3(C_ / 128, ROWS / 256), 256, GEMM_SMEM>>>(
        y, wpt, b_proj, out, C_, C_);
}